// round 1
// baseline (speedup 1.0000x reference)
#include <cuda_runtime.h>
#include <math.h>

#define S_LEN 4096
#define HID 4096
#define NH 32
#define NKV 8
#define DH 128
#define HW 64
#define ATT_SCALE 0.08838834764831845f  // 1/sqrt(128)

// ---------------- scratch (static device allocations) ----------------
__device__ float g_Q[S_LEN * NH * DH];     // 64 MB
__device__ float g_K[S_LEN * NKV * DH];    // 16 MB
__device__ float g_V[S_LEN * NKV * DH];    // 16 MB
__device__ float g_attn[S_LEN * NH * DH];  // 64 MB

// ---------------- packed f32x2 helpers ----------------
__device__ __forceinline__ unsigned long long fma2(unsigned long long a,
                                                   unsigned long long b,
                                                   unsigned long long c) {
    unsigned long long d;
    asm("fma.rn.f32x2 %0, %1, %2, %3;" : "=l"(d) : "l"(a), "l"(b), "l"(c));
    return d;
}
__device__ __forceinline__ unsigned long long dup2(float a) {
    unsigned long long d;
    asm("mov.b64 %0, {%1, %1};" : "=l"(d) : "f"(a));
    return d;
}

// ---------------- SGEMM: C[M,N] = A[M,K] @ B[K,N], fp32 ----------------
// Tile 128(M) x 256(N) x 8(K), 256 threads, thread tile 8x16 via f32x2.
__global__ __launch_bounds__(256, 1)
void sgemm_kernel(const float* __restrict__ A, const float* __restrict__ B,
                  float* __restrict__ C, int M, int N, int K) {
    __shared__ float As[8][128];
    __shared__ float Bs[8][256];

    const int tid = threadIdx.x;
    const int m0 = blockIdx.y * 128;
    const int n0 = blockIdx.x * 256;
    const int tm = tid >> 4;            // 0..15
    const int tn = tid & 15;            // 0..15
    const int rm = tm * 8;

    // global load coords
    const int ar = tid >> 1;            // 0..127
    const int ac = (tid & 1) * 4;       // 0 or 4
    const int br = tid >> 6;            // 0..3
    const int bc = (tid & 63) * 4;      // 0..252

    const float* Aptr  = A + (size_t)(m0 + ar) * K + ac;
    const float* Bptr0 = B + (size_t)br * N + n0 + bc;
    const float* Bptr1 = B + (size_t)(br + 4) * N + n0 + bc;

    float4 pa  = *(const float4*)(Aptr);
    float4 pb0 = *(const float4*)(Bptr0);
    float4 pb1 = *(const float4*)(Bptr1);

    unsigned long long acc[8][8];
#pragma unroll
    for (int i = 0; i < 8; ++i)
#pragma unroll
        for (int j = 0; j < 8; ++j) acc[i][j] = 0ull;

    const int nkt = K >> 3;
    for (int kt = 0; kt < nkt; ++kt) {
        // commit prefetched tile to smem
        As[ac + 0][ar] = pa.x;
        As[ac + 1][ar] = pa.y;
        As[ac + 2][ar] = pa.z;
        As[ac + 3][ar] = pa.w;
        *(float4*)&Bs[br][bc]     = pb0;
        *(float4*)&Bs[br + 4][bc] = pb1;
        __syncthreads();

        if (kt + 1 < nkt) {
            pa  = *(const float4*)(Aptr + (size_t)(kt + 1) * 8);
            pb0 = *(const float4*)(Bptr0 + (size_t)(kt + 1) * 8 * N);
            pb1 = *(const float4*)(Bptr1 + (size_t)(kt + 1) * 8 * N);
        }

#pragma unroll
        for (int kk = 0; kk < 8; ++kk) {
            float av[8];
            *(float4*)&av[0] = *(const float4*)&As[kk][rm];
            *(float4*)&av[4] = *(const float4*)&As[kk][rm + 4];
            unsigned long long ap[8];
#pragma unroll
            for (int i = 0; i < 8; ++i) ap[i] = dup2(av[i]);

            unsigned long long bp[8];
#pragma unroll
            for (int j = 0; j < 4; ++j) {
                union { float4 f; unsigned long long u[2]; } ub;
                ub.f = *(const float4*)&Bs[kk][tn * 4 + 64 * j];
                bp[2 * j]     = ub.u[0];
                bp[2 * j + 1] = ub.u[1];
            }
#pragma unroll
            for (int i = 0; i < 8; ++i)
#pragma unroll
                for (int j = 0; j < 8; ++j)
                    acc[i][j] = fma2(ap[i], bp[j], acc[i][j]);
        }
        __syncthreads();
    }

#pragma unroll
    for (int i = 0; i < 8; ++i) {
        float* Crow = C + (size_t)(m0 + rm + i) * N + n0;
#pragma unroll
        for (int j = 0; j < 4; ++j) {
            union { float4 f; unsigned long long u[2]; } uo;
            uo.u[0] = acc[i][2 * j];
            uo.u[1] = acc[i][2 * j + 1];
            *(float4*)&Crow[tn * 4 + 64 * j] = uo.f;
        }
    }
}

// ---------------- RoPE (in place) ----------------
// X: [S][nh*128]; one block per position, 64 threads (one per freq), loop heads.
__global__ void rope_kernel(float* __restrict__ X, int nh) {
    const int s = blockIdx.x;
    const int d = threadIdx.x;  // 0..63
    const float e = (float)d * (1.0f / 64.0f);
    const float invf = 1.0f / powf(10000.0f, e);
    const float ang = (float)s * invf;
    float sn, cs;
    sincosf(ang, &sn, &cs);
    float* p = X + (size_t)s * nh * DH;
    for (int h = 0; h < nh; ++h) {
        const float x1 = p[d];
        const float x2 = p[d + 64];
        p[d]      = x1 * cs - x2 * sn;
        p[d + 64] = x2 * cs + x1 * sn;
        p += DH;
    }
}

// ---------------- local windowed attention ----------------
// grid (64 qblocks, 32 heads), 256 threads. Writes O = 0.7 * local_out.
// Each query p attends keys p-64..p; keys at pos<0 are zero vectors (score 0),
// included in softmax (matches reference zero-padding semantics).
#define QP 132
#define KP 132
__global__ __launch_bounds__(256, 1)
void local_attn_kernel(const float* __restrict__ Q, const float* __restrict__ K,
                       const float* __restrict__ V, float* __restrict__ O) {
    extern __shared__ float sm[];
    float* sq = sm;                    // 64 x 132
    float* sk = sq + 64 * QP;          // 128 x 132
    float* sv = sk + 128 * KP;         // 128 x 128
    float* sc = sv + 128 * 128;        // 64 x 66 (65 used)

    const int tid = threadIdx.x;
    const int h = blockIdx.y;
    const int n = blockIdx.x;
    const int kvh = h >> 2;
    const int q0 = n * 64;
    const int key0 = q0 - 64;

    // load Q block (64 x 128)
#pragma unroll
    for (int it = 0; it < 8; ++it) {
        int idx = tid + it * 256;
        int r = idx >> 5, c4 = idx & 31;
        float4 v4 = *(const float4*)&Q[(size_t)(q0 + r) * (NH * DH) + h * DH + c4 * 4];
        *(float4*)&sq[r * QP + c4 * 4] = v4;
    }
    // load K/V window (128 x 128), zero rows for pos<0
#pragma unroll
    for (int it = 0; it < 16; ++it) {
        int idx = tid + it * 256;
        int r = idx >> 5, c4 = idx & 31;
        int pos = key0 + r;
        float4 kv = make_float4(0.f, 0.f, 0.f, 0.f);
        float4 vv = make_float4(0.f, 0.f, 0.f, 0.f);
        if (pos >= 0) {
            kv = *(const float4*)&K[(size_t)pos * (NKV * DH) + kvh * DH + c4 * 4];
            vv = *(const float4*)&V[(size_t)pos * (NKV * DH) + kvh * DH + c4 * 4];
        }
        *(float4*)&sk[r * KP + c4 * 4] = kv;
        *(float4*)&sv[r * 128 + c4 * 4] = vv;
    }
    __syncthreads();

    // scores: thread -> query i = tid/4, key offsets jj = (tid&3) + 4m
    {
        const int i = tid >> 2;
        const int jo = tid & 3;
        float s[16];
        float s64 = 0.f;
#pragma unroll
        for (int m = 0; m < 16; ++m) s[m] = 0.f;
        const float* qrow = sq + i * QP;
        for (int d0 = 0; d0 < 128; d0 += 8) {
            float qv[8];
            *(float4*)&qv[0] = *(const float4*)&qrow[d0];
            *(float4*)&qv[4] = *(const float4*)&qrow[d0 + 4];
#pragma unroll
            for (int m = 0; m < 16; ++m) {
                const float* kr = sk + (i + jo + 4 * m) * KP + d0;
#pragma unroll
                for (int dd = 0; dd < 8; ++dd) s[m] = fmaf(qv[dd], kr[dd], s[m]);
            }
            if (jo == 0) {
                const float* kr = sk + (i + 64) * KP + d0;
#pragma unroll
                for (int dd = 0; dd < 8; ++dd) s64 = fmaf(qv[dd], kr[dd], s64);
            }
        }
#pragma unroll
        for (int m = 0; m < 16; ++m) sc[i * 66 + jo + 4 * m] = s[m] * ATT_SCALE;
        if (jo == 0) sc[i * 66 + 64] = s64 * ATT_SCALE;
    }
    __syncthreads();

    // softmax over 65 slots per query
    if (tid < 64) {
        float* row = sc + tid * 66;
        float mx = row[0];
        for (int j = 1; j < 65; ++j) mx = fmaxf(mx, row[j]);
        float sum = 0.f;
        for (int j = 0; j < 65; ++j) {
            float ex = expf(row[j] - mx);
            row[j] = ex;
            sum += ex;
        }
        float inv = 1.f / sum;
        for (int j = 0; j < 65; ++j) row[j] *= inv;
    }
    __syncthreads();

    // AV: warp per 8 queries, lanes split D as float4
    {
        const int w = tid >> 5, lane = tid & 31;
        const float4* sv4 = (const float4*)sv;
        for (int iq = 0; iq < 8; ++iq) {
            const int i = w * 8 + iq;
            const float* wrow = sc + i * 66;
            float4 o = make_float4(0.f, 0.f, 0.f, 0.f);
#pragma unroll 5
            for (int jj = 0; jj < 65; ++jj) {
                float wt = wrow[jj];
                float4 v4 = sv4[(i + jj) * 32 + lane];
                o.x = fmaf(wt, v4.x, o.x);
                o.y = fmaf(wt, v4.y, o.y);
                o.z = fmaf(wt, v4.z, o.z);
                o.w = fmaf(wt, v4.w, o.w);
            }
            float4 res = make_float4(0.7f * o.x, 0.7f * o.y, 0.7f * o.z, 0.7f * o.w);
            *(float4*)&O[(size_t)(q0 + i) * (NH * DH) + h * DH + lane * 4] = res;
        }
    }
}

// ---------------- landmark (global) attention ----------------
// grid (64 query chunks, 32 heads), 256 threads. O += 0.3 * global_out.
// Landmarks at positions j*64; query chunk c sees landmarks 0..c.
__global__ __launch_bounds__(256, 1)
void lm_attn_kernel(const float* __restrict__ Q, const float* __restrict__ K,
                    const float* __restrict__ V, float* __restrict__ O) {
    extern __shared__ float sm[];
    float* sq  = sm;                   // 64 x 132
    float* slk = sq + 64 * QP;         // 64 x 132
    float* slv = slk + 64 * QP;        // 64 x 128
    float* sc  = slv + 64 * 128;       // 64 x 66

    const int tid = threadIdx.x;
    const int h = blockIdx.y;
    const int c = blockIdx.x;
    const int kvh = h >> 2;
    const int q0 = c * 64;
    const int nvis = c + 1;

#pragma unroll
    for (int it = 0; it < 8; ++it) {
        int idx = tid + it * 256;
        int r = idx >> 5, c4 = idx & 31;
        *(float4*)&sq[r * QP + c4 * 4] =
            *(const float4*)&Q[(size_t)(q0 + r) * (NH * DH) + h * DH + c4 * 4];
    }
#pragma unroll
    for (int it = 0; it < 8; ++it) {
        int idx = tid + it * 256;
        int r = idx >> 5, c4 = idx & 31;
        int pos = r * 64;  // landmark position
        *(float4*)&slk[r * QP + c4 * 4] =
            *(const float4*)&K[(size_t)pos * (NKV * DH) + kvh * DH + c4 * 4];
        *(float4*)&slv[r * 128 + c4 * 4] =
            *(const float4*)&V[(size_t)pos * (NKV * DH) + kvh * DH + c4 * 4];
    }
    __syncthreads();

    // scores (compute all 64, store only visible)
    {
        const int i = tid >> 2;
        const int jo = tid & 3;
        float s[16];
#pragma unroll
        for (int m = 0; m < 16; ++m) s[m] = 0.f;
        const float* qrow = sq + i * QP;
        for (int d0 = 0; d0 < 128; d0 += 8) {
            float qv[8];
            *(float4*)&qv[0] = *(const float4*)&qrow[d0];
            *(float4*)&qv[4] = *(const float4*)&qrow[d0 + 4];
#pragma unroll
            for (int m = 0; m < 16; ++m) {
                const float* kr = slk + (jo + 4 * m) * QP + d0;
#pragma unroll
                for (int dd = 0; dd < 8; ++dd) s[m] = fmaf(qv[dd], kr[dd], s[m]);
            }
        }
#pragma unroll
        for (int m = 0; m < 16; ++m) {
            int jj = jo + 4 * m;
            if (jj < nvis) sc[i * 66 + jj] = s[m] * ATT_SCALE;
        }
    }
    __syncthreads();

    if (tid < 64) {
        float* row = sc + tid * 66;
        float mx = row[0];
        for (int j = 1; j < nvis; ++j) mx = fmaxf(mx, row[j]);
        float sum = 0.f;
        for (int j = 0; j < nvis; ++j) {
            float ex = expf(row[j] - mx);
            row[j] = ex;
            sum += ex;
        }
        float inv = 1.f / sum;
        for (int j = 0; j < nvis; ++j) row[j] *= inv;
    }
    __syncthreads();

    {
        const int w = tid >> 5, lane = tid & 31;
        const float4* slv4 = (const float4*)slv;
        for (int iq = 0; iq < 8; ++iq) {
            const int i = w * 8 + iq;
            const float* wrow = sc + i * 66;
            float4 o = make_float4(0.f, 0.f, 0.f, 0.f);
            for (int jj = 0; jj < nvis; ++jj) {
                float wt = wrow[jj];
                float4 v4 = slv4[jj * 32 + lane];
                o.x = fmaf(wt, v4.x, o.x);
                o.y = fmaf(wt, v4.y, o.y);
                o.z = fmaf(wt, v4.z, o.z);
                o.w = fmaf(wt, v4.w, o.w);
            }
            float* dst = &O[(size_t)(q0 + i) * (NH * DH) + h * DH + lane * 4];
            float4 old = *(float4*)dst;
            old.x += 0.3f * o.x;
            old.y += 0.3f * o.y;
            old.z += 0.3f * o.z;
            old.w += 0.3f * o.w;
            *(float4*)dst = old;
        }
    }
}

// ---------------- launch ----------------
extern "C" void kernel_launch(void* const* d_in, const int* in_sizes, int n_in,
                              void* d_out, int out_size) {
    const float* hs = (const float*)d_in[0];
    const float* wq = (const float*)d_in[1];
    const float* wk = (const float*)d_in[2];
    const float* wv = (const float*)d_in[3];
    const float* wo = (const float*)d_in[4];
    float* out = (float*)d_out;

    float *Q, *K, *V, *AT;
    cudaGetSymbolAddress((void**)&Q, g_Q);
    cudaGetSymbolAddress((void**)&K, g_K);
    cudaGetSymbolAddress((void**)&V, g_V);
    cudaGetSymbolAddress((void**)&AT, g_attn);

    const int SMEM_LOCAL = (64 * QP + 128 * KP + 128 * 128 + 64 * 66) * 4;  // 183808
    const int SMEM_LM    = (64 * QP + 64 * QP + 64 * 128 + 64 * 66) * 4;    // 117248
    cudaFuncSetAttribute(local_attn_kernel,
                         cudaFuncAttributeMaxDynamicSharedMemorySize, SMEM_LOCAL);
    cudaFuncSetAttribute(lm_attn_kernel,
                         cudaFuncAttributeMaxDynamicSharedMemorySize, SMEM_LM);

    // projections
    sgemm_kernel<<<dim3(HID / 256, S_LEN / 128), 256>>>(hs, wq, Q, S_LEN, NH * DH, HID);
    sgemm_kernel<<<dim3((NKV * DH) / 256, S_LEN / 128), 256>>>(hs, wk, K, S_LEN, NKV * DH, HID);
    sgemm_kernel<<<dim3((NKV * DH) / 256, S_LEN / 128), 256>>>(hs, wv, V, S_LEN, NKV * DH, HID);

    // rope
    rope_kernel<<<S_LEN, 64>>>(Q, NH);
    rope_kernel<<<S_LEN, 64>>>(K, NKV);

    // attention: local writes 0.7*local, landmark adds 0.3*global
    local_attn_kernel<<<dim3(S_LEN / 64, NH), 256, SMEM_LOCAL>>>(Q, K, V, AT);
    lm_attn_kernel<<<dim3(S_LEN / 64, NH), 256, SMEM_LM>>>(Q, K, V, AT);

    // output projection
    sgemm_kernel<<<dim3(HID / 256, S_LEN / 128), 256>>>(AT, wo, out, S_LEN, HID, HID);
}

// round 3
// speedup vs baseline: 1.3557x; 1.3557x over previous
#include <cuda_runtime.h>
#include <cuda_bf16.h>
#include <math.h>
#include <stdint.h>

#define S_LEN 4096
#define HID 4096
#define NH 32
#define NKV 8
#define DH 128
#define ATT_SCALE 0.08838834764831845f  // 1/sqrt(128)

// ---------------- scratch (static device allocations) ----------------
__device__ float g_Q[S_LEN * NH * DH];
__device__ float g_K[S_LEN * NKV * DH];
__device__ float g_V[S_LEN * NKV * DH];
__device__ float g_attn[S_LEN * NH * DH];
__device__ __nv_bfloat16 g_hsHi[S_LEN * HID];
__device__ __nv_bfloat16 g_hsLo[S_LEN * HID];
__device__ __nv_bfloat16 g_wqTHi[HID * HID];
__device__ __nv_bfloat16 g_wqTLo[HID * HID];
__device__ __nv_bfloat16 g_wkTHi[(NKV * DH) * HID];
__device__ __nv_bfloat16 g_wkTLo[(NKV * DH) * HID];
__device__ __nv_bfloat16 g_wvTHi[(NKV * DH) * HID];
__device__ __nv_bfloat16 g_wvTLo[(NKV * DH) * HID];
__device__ __nv_bfloat16 g_woTHi[HID * HID];
__device__ __nv_bfloat16 g_woTLo[HID * HID];
__device__ __nv_bfloat16 g_atHi[S_LEN * NH * DH];
__device__ __nv_bfloat16 g_atLo[S_LEN * NH * DH];

// ================= helpers =================
__device__ __forceinline__ uint32_t smem_u32(const void* p) {
    uint32_t a;
    asm("{ .reg .u64 t; cvta.to.shared.u64 t, %1; cvt.u32.u64 %0, t; }" : "=r"(a) : "l"(p));
    return a;
}
__device__ __forceinline__ uint32_t swz(uint32_t o) { return o ^ ((o >> 3) & 0x70); }

__device__ __forceinline__ void ldsm_x4(uint32_t& r0, uint32_t& r1, uint32_t& r2, uint32_t& r3,
                                        uint32_t addr) {
    asm volatile("ldmatrix.sync.aligned.m8n8.x4.shared.b16 {%0, %1, %2, %3}, [%4];"
                 : "=r"(r0), "=r"(r1), "=r"(r2), "=r"(r3) : "r"(addr));
}
__device__ __forceinline__ void mma16816(float* c, const uint32_t* a, uint32_t b0, uint32_t b1) {
    asm volatile(
        "mma.sync.aligned.m16n8k16.row.col.f32.bf16.bf16.f32 "
        "{%0, %1, %2, %3}, {%4, %5, %6, %7}, {%8, %9}, {%0, %1, %2, %3};"
        : "+f"(c[0]), "+f"(c[1]), "+f"(c[2]), "+f"(c[3])
        : "r"(a[0]), "r"(a[1]), "r"(a[2]), "r"(a[3]), "r"(b0), "r"(b1));
}

// ================= conversion kernels =================
__global__ void split_kernel(const float* __restrict__ in,
                             __nv_bfloat16* __restrict__ hi,
                             __nv_bfloat16* __restrict__ lo) {
    int i = (blockIdx.x * 256 + threadIdx.x) * 4;
    float4 v = *(const float4*)&in[i];
    union { __nv_bfloat16 b[4]; uint2 u; } H, L;
    float f[4] = {v.x, v.y, v.z, v.w};
#pragma unroll
    for (int j = 0; j < 4; ++j) {
        __nv_bfloat16 h = __float2bfloat16(f[j]);
        H.b[j] = h;
        L.b[j] = __float2bfloat16(f[j] - __bfloat162float(h));
    }
    *(uint2*)&hi[i] = H.u;
    *(uint2*)&lo[i] = L.u;
}

// W [rows][cols] fp32 -> Wt hi/lo [cols][rows] bf16
__global__ void transpose_split_kernel(const float* __restrict__ W,
                                       __nv_bfloat16* __restrict__ hi,
                                       __nv_bfloat16* __restrict__ lo,
                                       int rows, int cols) {
    __shared__ float t[32][33];
    int c0 = blockIdx.x * 32, r0 = blockIdx.y * 32;
    int tx = threadIdx.x, ty = threadIdx.y;
#pragma unroll
    for (int j = 0; j < 4; ++j) {
        int r = ty + j * 8;
        t[r][tx] = W[(size_t)(r0 + r) * cols + c0 + tx];
    }
    __syncthreads();
#pragma unroll
    for (int j = 0; j < 4; ++j) {
        int r = ty + j * 8;
        float v = t[tx][r];
        __nv_bfloat16 h = __float2bfloat16(v);
        size_t o = (size_t)(c0 + r) * rows + r0 + tx;
        hi[o] = h;
        lo[o] = __float2bfloat16(v - __bfloat162float(h));
    }
}

// ================= HMMA split-bf16 GEMM =================
// C[M,N] = (Ahi+Alo)[M,K] @ (Bhi+Blo)[N,K]^T, 3-term split, fp32 accum.
// CTA 128x128, 512 thr (16 warps 4x4, warp tile 32x32), K-chunk 64, 2-stage smem.
#define STAGE 16384
#define SMEM_GEMM (8 * STAGE)

__global__ __launch_bounds__(512, 1)
void gemm_mma_kernel(const __nv_bfloat16* __restrict__ Ahi, const __nv_bfloat16* __restrict__ Alo,
                     const __nv_bfloat16* __restrict__ Bhi, const __nv_bfloat16* __restrict__ Blo,
                     float* __restrict__ C, int N, int K) {
    extern __shared__ char smem[];
    const uint32_t sb = smem_u32(smem);
    const int tid = threadIdx.x;
    const int lane = tid & 31;
    const int wid = tid >> 5;
    const int m0 = blockIdx.y * 128, n0 = blockIdx.x * 128;
    const int wm = (wid >> 2) * 32;  // warp m offset
    const int wn = (wid & 3) * 32;   // warp n offset

    // global->smem mapping: 2 slots of 16B per operand per thread per chunk
    const __nv_bfloat16* aptr[2];
    const __nv_bfloat16* bptr[2];
    uint32_t soff[2];
#pragma unroll
    for (int i = 0; i < 2; ++i) {
        int idx = tid + i * 512;
        int r = idx >> 3, c = idx & 7;
        aptr[i] = Ahi + (size_t)(m0 + r) * K + c * 8;
        bptr[i] = Bhi + (size_t)(n0 + r) * K + c * 8;
        soff[i] = swz(r * 128 + c * 16);
    }
    const ptrdiff_t dA = Alo - Ahi;
    const ptrdiff_t dB = Blo - Bhi;

    float acc[2][4][4];
#pragma unroll
    for (int mt = 0; mt < 2; ++mt)
#pragma unroll
        for (int nt = 0; nt < 4; ++nt)
#pragma unroll
            for (int q = 0; q < 4; ++q) acc[mt][nt][q] = 0.f;

    // per-lane ldmatrix row pattern: quadrants (q&1)->row+8, (q>>1)->k+16B
    const int row_off = ((lane >> 3) & 1) * 8 + (lane & 7);
    const int kxtra = (lane >> 4) * 16;
    const uint32_t a_lbase = (uint32_t)((wm + row_off) * 128 + kxtra);
    const uint32_t b_lbase = (uint32_t)((wn + row_off) * 128 + kxtra);

    uint4 rg[8];  // Ah0 Ah1 Al0 Al1 Bh0 Bh1 Bl0 Bl1
#pragma unroll
    for (int i = 0; i < 2; ++i) {
        rg[0 + i] = *(const uint4*)(aptr[i]);
        rg[2 + i] = *(const uint4*)(aptr[i] + dA);
        rg[4 + i] = *(const uint4*)(bptr[i]);
        rg[6 + i] = *(const uint4*)(bptr[i] + dB);
    }

    const int NKT = K >> 6;
    for (int kt = 0; kt < NKT; ++kt) {
        const uint32_t st = sb + (uint32_t)(kt & 1) * (4 * STAGE);
        char* stc = smem + (size_t)(kt & 1) * (4 * STAGE);
#pragma unroll
        for (int i = 0; i < 2; ++i) {
            *(uint4*)(stc + soff[i]) = rg[0 + i];
            *(uint4*)(stc + STAGE + soff[i]) = rg[2 + i];
            *(uint4*)(stc + 2 * STAGE + soff[i]) = rg[4 + i];
            *(uint4*)(stc + 3 * STAGE + soff[i]) = rg[6 + i];
        }
        __syncthreads();
        if (kt + 1 < NKT) {
            const int ko = (kt + 1) * 64;
#pragma unroll
            for (int i = 0; i < 2; ++i) {
                rg[0 + i] = *(const uint4*)(aptr[i] + ko);
                rg[2 + i] = *(const uint4*)(aptr[i] + dA + ko);
                rg[4 + i] = *(const uint4*)(bptr[i] + ko);
                rg[6 + i] = *(const uint4*)(bptr[i] + dB + ko);
            }
        }
        // 3 passes: (Ah,Bh), (Ah,Bl), (Al,Bh)
#pragma unroll
        for (int p = 0; p < 3; ++p) {
            const uint32_t Ab = st + (p == 2 ? STAGE : 0);
            const uint32_t Bb = st + (p == 1 ? 3 * STAGE : 2 * STAGE);
#pragma unroll
            for (int ks = 0; ks < 4; ++ks) {
                uint32_t a[2][4], b[2][4];
#pragma unroll
                for (int mt = 0; mt < 2; ++mt)
                    ldsm_x4(a[mt][0], a[mt][1], a[mt][2], a[mt][3],
                            Ab + swz(a_lbase + mt * 16 * 128 + ks * 32));
#pragma unroll
                for (int nt2 = 0; nt2 < 2; ++nt2)
                    ldsm_x4(b[nt2][0], b[nt2][1], b[nt2][2], b[nt2][3],
                            Bb + swz(b_lbase + nt2 * 16 * 128 + ks * 32));
#pragma unroll
                for (int mt = 0; mt < 2; ++mt)
#pragma unroll
                    for (int nt = 0; nt < 4; ++nt)
                        mma16816(acc[mt][nt], a[mt],
                                 b[nt >> 1][nt & 1], b[nt >> 1][2 + (nt & 1)]);
            }
        }
    }

    // epilogue
#pragma unroll
    for (int mt = 0; mt < 2; ++mt) {
        const int row = m0 + wm + mt * 16 + (lane >> 2);
#pragma unroll
        for (int nt = 0; nt < 4; ++nt) {
            const int col = n0 + wn + nt * 8 + (lane & 3) * 2;
            float* p0 = C + (size_t)row * N + col;
            *(float2*)p0 = make_float2(acc[mt][nt][0], acc[mt][nt][1]);
            *(float2*)(p0 + 8 * (size_t)N) = make_float2(acc[mt][nt][2], acc[mt][nt][3]);
        }
    }
}

// ---------------- RoPE (in place) ----------------
__global__ void rope_kernel(float* __restrict__ X, int nh) {
    const int s = blockIdx.x;
    const int d = threadIdx.x;  // 0..63
    const float e = (float)d * (1.0f / 64.0f);
    const float invf = 1.0f / powf(10000.0f, e);
    const float ang = (float)s * invf;
    float sn, cs;
    sincosf(ang, &sn, &cs);
    float* p = X + (size_t)s * nh * DH;
    for (int h = 0; h < nh; ++h) {
        const float x1 = p[d];
        const float x2 = p[d + 64];
        p[d] = x1 * cs - x2 * sn;
        p[d + 64] = x2 * cs + x1 * sn;
        p += DH;
    }
}

// ---------------- local windowed attention ----------------
#define QP 132
#define KP 132
__global__ __launch_bounds__(256, 1)
void local_attn_kernel(const float* __restrict__ Q, const float* __restrict__ K,
                       const float* __restrict__ V, float* __restrict__ O) {
    extern __shared__ float sm[];
    float* sq = sm;                    // 64 x 132
    float* sk = sq + 64 * QP;          // 128 x 132
    float* sv = sk + 128 * KP;         // 128 x 128
    float* sc = sv + 128 * 128;        // 64 x 66

    const int tid = threadIdx.x;
    const int h = blockIdx.y;
    const int n = blockIdx.x;
    const int kvh = h >> 2;
    const int q0 = n * 64;
    const int key0 = q0 - 64;

#pragma unroll
    for (int it = 0; it < 8; ++it) {
        int idx = tid + it * 256;
        int r = idx >> 5, c4 = idx & 31;
        float4 v4 = *(const float4*)&Q[(size_t)(q0 + r) * (NH * DH) + h * DH + c4 * 4];
        *(float4*)&sq[r * QP + c4 * 4] = v4;
    }
#pragma unroll
    for (int it = 0; it < 16; ++it) {
        int idx = tid + it * 256;
        int r = idx >> 5, c4 = idx & 31;
        int pos = key0 + r;
        float4 kv = make_float4(0.f, 0.f, 0.f, 0.f);
        float4 vv = make_float4(0.f, 0.f, 0.f, 0.f);
        if (pos >= 0) {
            kv = *(const float4*)&K[(size_t)pos * (NKV * DH) + kvh * DH + c4 * 4];
            vv = *(const float4*)&V[(size_t)pos * (NKV * DH) + kvh * DH + c4 * 4];
        }
        *(float4*)&sk[r * KP + c4 * 4] = kv;
        *(float4*)&sv[r * 128 + c4 * 4] = vv;
    }
    __syncthreads();

    {
        const int i = tid >> 2;
        const int jo = tid & 3;
        float s[16];
        float s64 = 0.f;
#pragma unroll
        for (int m = 0; m < 16; ++m) s[m] = 0.f;
        const float* qrow = sq + i * QP;
        for (int d0 = 0; d0 < 128; d0 += 8) {
            float qv[8];
            *(float4*)&qv[0] = *(const float4*)&qrow[d0];
            *(float4*)&qv[4] = *(const float4*)&qrow[d0 + 4];
#pragma unroll
            for (int m = 0; m < 16; ++m) {
                const float* kr = sk + (i + jo + 4 * m) * KP + d0;
#pragma unroll
                for (int dd = 0; dd < 8; ++dd) s[m] = fmaf(qv[dd], kr[dd], s[m]);
            }
            if (jo == 0) {
                const float* kr = sk + (i + 64) * KP + d0;
#pragma unroll
                for (int dd = 0; dd < 8; ++dd) s64 = fmaf(qv[dd], kr[dd], s64);
            }
        }
#pragma unroll
        for (int m = 0; m < 16; ++m) sc[i * 66 + jo + 4 * m] = s[m] * ATT_SCALE;
        if (jo == 0) sc[i * 66 + 64] = s64 * ATT_SCALE;
    }
    __syncthreads();

    if (tid < 64) {
        float* row = sc + tid * 66;
        float mx = row[0];
        for (int j = 1; j < 65; ++j) mx = fmaxf(mx, row[j]);
        float sum = 0.f;
        for (int j = 0; j < 65; ++j) {
            float ex = expf(row[j] - mx);
            row[j] = ex;
            sum += ex;
        }
        float inv = 1.f / sum;
        for (int j = 0; j < 65; ++j) row[j] *= inv;
    }
    __syncthreads();

    {
        const int w = tid >> 5, lane = tid & 31;
        const float4* sv4 = (const float4*)sv;
        for (int iq = 0; iq < 8; ++iq) {
            const int i = w * 8 + iq;
            const float* wrow = sc + i * 66;
            float4 o = make_float4(0.f, 0.f, 0.f, 0.f);
#pragma unroll 5
            for (int jj = 0; jj < 65; ++jj) {
                float wt = wrow[jj];
                float4 v4 = sv4[(i + jj) * 32 + lane];
                o.x = fmaf(wt, v4.x, o.x);
                o.y = fmaf(wt, v4.y, o.y);
                o.z = fmaf(wt, v4.z, o.z);
                o.w = fmaf(wt, v4.w, o.w);
            }
            float4 res = make_float4(0.7f * o.x, 0.7f * o.y, 0.7f * o.z, 0.7f * o.w);
            *(float4*)&O[(size_t)(q0 + i) * (NH * DH) + h * DH + lane * 4] = res;
        }
    }
}

// ---------------- landmark attention (adds 0.3*global, writes bf16 hi/lo) ----------------
__global__ __launch_bounds__(256, 1)
void lm_attn_kernel(const float* __restrict__ Q, const float* __restrict__ K,
                    const float* __restrict__ V, const float* __restrict__ OL,
                    __nv_bfloat16* __restrict__ atHi, __nv_bfloat16* __restrict__ atLo) {
    extern __shared__ float sm[];
    float* sq = sm;                    // 64 x 132
    float* slk = sq + 64 * QP;         // 64 x 132
    float* slv = slk + 64 * QP;        // 64 x 128
    float* sc = slv + 64 * 128;        // 64 x 66

    const int tid = threadIdx.x;
    const int h = blockIdx.y;
    const int c = blockIdx.x;
    const int kvh = h >> 2;
    const int q0 = c * 64;
    const int nvis = c + 1;

#pragma unroll
    for (int it = 0; it < 8; ++it) {
        int idx = tid + it * 256;
        int r = idx >> 5, c4 = idx & 31;
        *(float4*)&sq[r * QP + c4 * 4] =
            *(const float4*)&Q[(size_t)(q0 + r) * (NH * DH) + h * DH + c4 * 4];
    }
#pragma unroll
    for (int it = 0; it < 8; ++it) {
        int idx = tid + it * 256;
        int r = idx >> 5, c4 = idx & 31;
        int pos = r * 64;
        *(float4*)&slk[r * QP + c4 * 4] =
            *(const float4*)&K[(size_t)pos * (NKV * DH) + kvh * DH + c4 * 4];
        *(float4*)&slv[r * 128 + c4 * 4] =
            *(const float4*)&V[(size_t)pos * (NKV * DH) + kvh * DH + c4 * 4];
    }
    __syncthreads();

    {
        const int i = tid >> 2;
        const int jo = tid & 3;
        float s[16];
#pragma unroll
        for (int m = 0; m < 16; ++m) s[m] = 0.f;
        const float* qrow = sq + i * QP;
        for (int d0 = 0; d0 < 128; d0 += 8) {
            float qv[8];
            *(float4*)&qv[0] = *(const float4*)&qrow[d0];
            *(float4*)&qv[4] = *(const float4*)&qrow[d0 + 4];
#pragma unroll
            for (int m = 0; m < 16; ++m) {
                const float* kr = slk + (jo + 4 * m) * QP + d0;
#pragma unroll
                for (int dd = 0; dd < 8; ++dd) s[m] = fmaf(qv[dd], kr[dd], s[m]);
            }
        }
#pragma unroll
        for (int m = 0; m < 16; ++m) {
            int jj = jo + 4 * m;
            if (jj < nvis) sc[i * 66 + jj] = s[m] * ATT_SCALE;
        }
    }
    __syncthreads();

    if (tid < 64) {
        float* row = sc + tid * 66;
        float mx = row[0];
        for (int j = 1; j < nvis; ++j) mx = fmaxf(mx, row[j]);
        float sum = 0.f;
        for (int j = 0; j < nvis; ++j) {
            float ex = expf(row[j] - mx);
            row[j] = ex;
            sum += ex;
        }
        float inv = 1.f / sum;
        for (int j = 0; j < nvis; ++j) row[j] *= inv;
    }
    __syncthreads();

    {
        const int w = tid >> 5, lane = tid & 31;
        const float4* slv4 = (const float4*)slv;
        for (int iq = 0; iq < 8; ++iq) {
            const int i = w * 8 + iq;
            const float* wrow = sc + i * 66;
            float4 o = make_float4(0.f, 0.f, 0.f, 0.f);
            for (int jj = 0; jj < nvis; ++jj) {
                float wt = wrow[jj];
                float4 v4 = slv4[jj * 32 + lane];
                o.x = fmaf(wt, v4.x, o.x);
                o.y = fmaf(wt, v4.y, o.y);
                o.z = fmaf(wt, v4.z, o.z);
                o.w = fmaf(wt, v4.w, o.w);
            }
            size_t idx = (size_t)(q0 + i) * (NH * DH) + h * DH + lane * 4;
            float4 old = *(const float4*)&OL[idx];
            float s4[4] = {old.x + 0.3f * o.x, old.y + 0.3f * o.y,
                           old.z + 0.3f * o.z, old.w + 0.3f * o.w};
            union { __nv_bfloat16 b[4]; uint2 u; } H, L;
#pragma unroll
            for (int q = 0; q < 4; ++q) {
                __nv_bfloat16 hb = __float2bfloat16(s4[q]);
                H.b[q] = hb;
                L.b[q] = __float2bfloat16(s4[q] - __bfloat162float(hb));
            }
            *(uint2*)&atHi[idx] = H.u;
            *(uint2*)&atLo[idx] = L.u;
        }
    }
}

// ---------------- launch ----------------
extern "C" void kernel_launch(void* const* d_in, const int* in_sizes, int n_in,
                              void* d_out, int out_size) {
    const float* hs = (const float*)d_in[0];
    const float* wq = (const float*)d_in[1];
    const float* wk = (const float*)d_in[2];
    const float* wv = (const float*)d_in[3];
    const float* wo = (const float*)d_in[4];
    float* out = (float*)d_out;

    float *Q, *K, *V, *AT;
    __nv_bfloat16 *hsHi, *hsLo, *wqTHi, *wqTLo, *wkTHi, *wkTLo, *wvTHi, *wvTLo,
        *woTHi, *woTLo, *atHi, *atLo;
    cudaGetSymbolAddress((void**)&Q, g_Q);
    cudaGetSymbolAddress((void**)&K, g_K);
    cudaGetSymbolAddress((void**)&V, g_V);
    cudaGetSymbolAddress((void**)&AT, g_attn);
    cudaGetSymbolAddress((void**)&hsHi, g_hsHi);
    cudaGetSymbolAddress((void**)&hsLo, g_hsLo);
    cudaGetSymbolAddress((void**)&wqTHi, g_wqTHi);
    cudaGetSymbolAddress((void**)&wqTLo, g_wqTLo);
    cudaGetSymbolAddress((void**)&wkTHi, g_wkTHi);
    cudaGetSymbolAddress((void**)&wkTLo, g_wkTLo);
    cudaGetSymbolAddress((void**)&wvTHi, g_wvTHi);
    cudaGetSymbolAddress((void**)&wvTLo, g_wvTLo);
    cudaGetSymbolAddress((void**)&woTHi, g_woTHi);
    cudaGetSymbolAddress((void**)&woTLo, g_woTLo);
    cudaGetSymbolAddress((void**)&atHi, g_atHi);
    cudaGetSymbolAddress((void**)&atLo, g_atLo);

    const int SMEM_LOCAL = (64 * QP + 128 * KP + 128 * 128 + 64 * 66) * 4;
    const int SMEM_LM = (64 * QP + 64 * QP + 64 * 128 + 64 * 66) * 4;
    cudaFuncSetAttribute(local_attn_kernel, cudaFuncAttributeMaxDynamicSharedMemorySize, SMEM_LOCAL);
    cudaFuncSetAttribute(lm_attn_kernel, cudaFuncAttributeMaxDynamicSharedMemorySize, SMEM_LM);
    cudaFuncSetAttribute(gemm_mma_kernel, cudaFuncAttributeMaxDynamicSharedMemorySize, SMEM_GEMM);

    // conversions
    split_kernel<<<(S_LEN * HID) / 1024, 256>>>(hs, hsHi, hsLo);
    transpose_split_kernel<<<dim3(HID / 32, HID / 32), dim3(32, 8)>>>(wq, wqTHi, wqTLo, HID, HID);
    transpose_split_kernel<<<dim3((NKV * DH) / 32, HID / 32), dim3(32, 8)>>>(wk, wkTHi, wkTLo, HID, NKV * DH);
    transpose_split_kernel<<<dim3((NKV * DH) / 32, HID / 32), dim3(32, 8)>>>(wv, wvTHi, wvTLo, HID, NKV * DH);
    transpose_split_kernel<<<dim3(HID / 32, HID / 32), dim3(32, 8)>>>(wo, woTHi, woTLo, HID, HID);

    // projections (HMMA split-bf16)
    gemm_mma_kernel<<<dim3((NH * DH) / 128, S_LEN / 128), 512, SMEM_GEMM>>>(
        hsHi, hsLo, wqTHi, wqTLo, Q, NH * DH, HID);
    gemm_mma_kernel<<<dim3((NKV * DH) / 128, S_LEN / 128), 512, SMEM_GEMM>>>(
        hsHi, hsLo, wkTHi, wkTLo, K, NKV * DH, HID);
    gemm_mma_kernel<<<dim3((NKV * DH) / 128, S_LEN / 128), 512, SMEM_GEMM>>>(
        hsHi, hsLo, wvTHi, wvTLo, V, NKV * DH, HID);

    // rope
    rope_kernel<<<S_LEN, 64>>>(Q, NH);
    rope_kernel<<<S_LEN, 64>>>(K, NKV);

    // attention
    local_attn_kernel<<<dim3(S_LEN / 64, NH), 256, SMEM_LOCAL>>>(Q, K, V, AT);
    lm_attn_kernel<<<dim3(S_LEN / 64, NH), 256, SMEM_LM>>>(Q, K, V, AT, atHi, atLo);

    // output projection
    gemm_mma_kernel<<<dim3(HID / 128, S_LEN / 128), 512, SMEM_GEMM>>>(
        atHi, atLo, woTHi, woTLo, out, HID, HID);
}

// round 4
// speedup vs baseline: 2.4860x; 1.8338x over previous
#include <cuda_runtime.h>
#include <cuda_bf16.h>
#include <cuda_fp16.h>
#include <math.h>
#include <stdint.h>

#define S_LEN 4096
#define HID 4096
#define NH 32
#define NKV 8
#define DH 128
#define ATT_SCALE 0.08838834764831845f  // 1/sqrt(128)

// ---------------- scratch (static device allocations) ----------------
__device__ float g_Q[S_LEN * NH * DH];
__device__ float g_K[S_LEN * NKV * DH];
__device__ float g_V[S_LEN * NKV * DH];
__device__ float g_attn[S_LEN * NH * DH];
__device__ __nv_bfloat16 g_hsHi[S_LEN * HID];
__device__ __nv_bfloat16 g_hsLo[S_LEN * HID];
__device__ __nv_bfloat16 g_wqTHi[HID * HID];
__device__ __nv_bfloat16 g_wqTLo[HID * HID];
__device__ __nv_bfloat16 g_wkTHi[(NKV * DH) * HID];
__device__ __nv_bfloat16 g_wkTLo[(NKV * DH) * HID];
__device__ __nv_bfloat16 g_wvTHi[(NKV * DH) * HID];
__device__ __nv_bfloat16 g_wvTLo[(NKV * DH) * HID];
__device__ __half g_woT16[HID * HID];
__device__ __half g_at16h[S_LEN * NH * DH];
__device__ __half g_at16l[S_LEN * NH * DH];

// ================= helpers =================
__device__ __forceinline__ uint32_t smem_u32(const void* p) {
    uint32_t a;
    asm("{ .reg .u64 t; cvta.to.shared.u64 t, %1; cvt.u32.u64 %0, t; }" : "=r"(a) : "l"(p));
    return a;
}
__device__ __forceinline__ uint32_t swz(uint32_t o) { return o ^ ((o >> 3) & 0x70); }

__device__ __forceinline__ void ldsm_x4(uint32_t& r0, uint32_t& r1, uint32_t& r2, uint32_t& r3,
                                        uint32_t addr) {
    asm volatile("ldmatrix.sync.aligned.m8n8.x4.shared.b16 {%0, %1, %2, %3}, [%4];"
                 : "=r"(r0), "=r"(r1), "=r"(r2), "=r"(r3) : "r"(addr));
}

template <typename T> struct MmaOp;
template <> struct MmaOp<__nv_bfloat16> {
    static __device__ __forceinline__ void run(float* c, const uint32_t* a, uint32_t b0,
                                               uint32_t b1) {
        asm volatile(
            "mma.sync.aligned.m16n8k16.row.col.f32.bf16.bf16.f32 "
            "{%0, %1, %2, %3}, {%4, %5, %6, %7}, {%8, %9}, {%0, %1, %2, %3};"
            : "+f"(c[0]), "+f"(c[1]), "+f"(c[2]), "+f"(c[3])
            : "r"(a[0]), "r"(a[1]), "r"(a[2]), "r"(a[3]), "r"(b0), "r"(b1));
    }
};
template <> struct MmaOp<__half> {
    static __device__ __forceinline__ void run(float* c, const uint32_t* a, uint32_t b0,
                                               uint32_t b1) {
        asm volatile(
            "mma.sync.aligned.m16n8k16.row.col.f32.f16.f16.f32 "
            "{%0, %1, %2, %3}, {%4, %5, %6, %7}, {%8, %9}, {%0, %1, %2, %3};"
            : "+f"(c[0]), "+f"(c[1]), "+f"(c[2]), "+f"(c[3])
            : "r"(a[0]), "r"(a[1]), "r"(a[2]), "r"(a[3]), "r"(b0), "r"(b1));
    }
};

__device__ __forceinline__ void cp16(uint32_t dst, const void* src) {
    asm volatile("cp.async.cg.shared.global [%0], [%1], 16;" :: "r"(dst), "l"(src));
}
#define CP_COMMIT() asm volatile("cp.async.commit_group;" ::: "memory")
#define CP_WAIT1() asm volatile("cp.async.wait_group 1;" ::: "memory")

// ================= conversion kernels =================
__global__ void split_kernel(const float* __restrict__ in,
                             __nv_bfloat16* __restrict__ hi,
                             __nv_bfloat16* __restrict__ lo) {
    int i = (blockIdx.x * 256 + threadIdx.x) * 4;
    float4 v = *(const float4*)&in[i];
    union { __nv_bfloat16 b[4]; uint2 u; } H, L;
    float f[4] = {v.x, v.y, v.z, v.w};
#pragma unroll
    for (int j = 0; j < 4; ++j) {
        __nv_bfloat16 h = __float2bfloat16(f[j]);
        H.b[j] = h;
        L.b[j] = __float2bfloat16(f[j] - __bfloat162float(h));
    }
    *(uint2*)&hi[i] = H.u;
    *(uint2*)&lo[i] = L.u;
}

// W [rows][cols] fp32 -> Wt hi/lo [cols][rows] bf16
__global__ void transpose_split_kernel(const float* __restrict__ W,
                                       __nv_bfloat16* __restrict__ hi,
                                       __nv_bfloat16* __restrict__ lo,
                                       int rows, int cols) {
    __shared__ float t[32][33];
    int c0 = blockIdx.x * 32, r0 = blockIdx.y * 32;
    int tx = threadIdx.x, ty = threadIdx.y;
#pragma unroll
    for (int j = 0; j < 4; ++j) {
        int r = ty + j * 8;
        t[r][tx] = W[(size_t)(r0 + r) * cols + c0 + tx];
    }
    __syncthreads();
#pragma unroll
    for (int j = 0; j < 4; ++j) {
        int r = ty + j * 8;
        float v = t[tx][r];
        __nv_bfloat16 h = __float2bfloat16(v);
        size_t o = (size_t)(c0 + r) * rows + r0 + tx;
        hi[o] = h;
        lo[o] = __float2bfloat16(v - __bfloat162float(h));
    }
}

// W [rows][cols] fp32 -> Wt [cols][rows] fp16 (single rounding)
__global__ void transpose_f16_kernel(const float* __restrict__ W,
                                     __half* __restrict__ out, int rows, int cols) {
    __shared__ float t[32][33];
    int c0 = blockIdx.x * 32, r0 = blockIdx.y * 32;
    int tx = threadIdx.x, ty = threadIdx.y;
#pragma unroll
    for (int j = 0; j < 4; ++j) {
        int r = ty + j * 8;
        t[r][tx] = W[(size_t)(r0 + r) * cols + c0 + tx];
    }
    __syncthreads();
#pragma unroll
    for (int j = 0; j < 4; ++j) {
        int r = ty + j * 8;
        out[(size_t)(c0 + r) * rows + r0 + tx] = __float2half_rn(t[tx][r]);
    }
}

// ================= HMMA GEMM (cp.async 2-stage, 2 CTAs/SM) =================
// C[M,N] = A[M,K] @ B[N,K]^T with A = Ahi+Alo split.
// SPLIT_B=true : 3-pass (Ah*Bh + Ah*Bl + Al*Bh)
// SPLIT_B=false: 2-pass (Ah*Bh + Al*Bh), B single-rounded
// CTA 128x64, 256 thr (8 warps 4x2, warp tile 32x32), K-chunk 64.
template <typename T, bool SPLIT_B>
__global__ __launch_bounds__(256, 2)
void gemm_tc(const T* __restrict__ Ahi, const T* __restrict__ Alo,
             const T* __restrict__ Bhi, const T* __restrict__ Blo,
             float* __restrict__ C, int N, int K) {
    constexpr uint32_t B_OFF = 32768;                       // A hi+lo = 32KB
    constexpr uint32_t STG = B_OFF + (SPLIT_B ? 16384 : 8192);
    extern __shared__ char smem[];
    const uint32_t sb = smem_u32(smem);
    const int tid = threadIdx.x, lane = tid & 31, wid = tid >> 5;
    const int m0 = blockIdx.y * 128, n0 = blockIdx.x * 64;
    const int wm = (wid >> 1) * 32, wn = (wid & 1) * 32;

    const T* aptr[4];
    uint32_t asw[4];
#pragma unroll
    for (int i = 0; i < 4; ++i) {
        int idx = tid + (i << 8);
        int r = idx >> 3, c = idx & 7;
        aptr[i] = Ahi + (size_t)(m0 + r) * K + (c << 3);
        asw[i] = swz(r * 128 + c * 16);
    }
    const T* bptr[2];
    uint32_t bsw[2];
#pragma unroll
    for (int i = 0; i < 2; ++i) {
        int idx = tid + (i << 8);
        int r = idx >> 3, c = idx & 7;
        bptr[i] = Bhi + (size_t)(n0 + r) * K + (c << 3);
        bsw[i] = swz(r * 128 + c * 16);
    }
    const ptrdiff_t dA = Alo - Ahi;
    const ptrdiff_t dB = SPLIT_B ? (Blo - Bhi) : 0;

    float acc[2][4][4];
#pragma unroll
    for (int mt = 0; mt < 2; ++mt)
#pragma unroll
        for (int nt = 0; nt < 4; ++nt)
#pragma unroll
            for (int q = 0; q < 4; ++q) acc[mt][nt][q] = 0.f;

    const int NKT = K >> 6;
    // prologue: stages 0,1
#pragma unroll
    for (int s = 0; s < 2; ++s) {
        const uint32_t st = sb + s * STG;
        const int ko = s * 64;
#pragma unroll
        for (int i = 0; i < 4; ++i) {
            cp16(st + asw[i], aptr[i] + ko);
            cp16(st + 16384 + asw[i], aptr[i] + dA + ko);
        }
#pragma unroll
        for (int i = 0; i < 2; ++i) {
            cp16(st + B_OFF + bsw[i], bptr[i] + ko);
            if (SPLIT_B) cp16(st + B_OFF + 8192 + bsw[i], bptr[i] + dB + ko);
        }
        CP_COMMIT();
    }

    const int row_off = ((lane >> 3) & 1) * 8 + (lane & 7);
    const int kxtra = (lane >> 4) * 16;
    const uint32_t a_lb = (uint32_t)((wm + row_off) * 128 + kxtra);
    const uint32_t b_lb = (uint32_t)((wn + row_off) * 128 + kxtra);

    for (int kt = 0; kt < NKT; ++kt) {
        CP_WAIT1();
        __syncthreads();
        const uint32_t st = sb + (uint32_t)(kt & 1) * STG;
#pragma unroll
        for (int ks = 0; ks < 4; ++ks) {
            uint32_t ah[2][4], al[2][4], bh[2][4];
#pragma unroll
            for (int mt = 0; mt < 2; ++mt) {
                uint32_t off = swz(a_lb + mt * 2048 + ks * 32);
                ldsm_x4(ah[mt][0], ah[mt][1], ah[mt][2], ah[mt][3], st + off);
                ldsm_x4(al[mt][0], al[mt][1], al[mt][2], al[mt][3], st + 16384 + off);
            }
#pragma unroll
            for (int nt2 = 0; nt2 < 2; ++nt2)
                ldsm_x4(bh[nt2][0], bh[nt2][1], bh[nt2][2], bh[nt2][3],
                        st + B_OFF + swz(b_lb + nt2 * 2048 + ks * 32));
            if (SPLIT_B) {
                uint32_t bl[2][4];
#pragma unroll
                for (int nt2 = 0; nt2 < 2; ++nt2)
                    ldsm_x4(bl[nt2][0], bl[nt2][1], bl[nt2][2], bl[nt2][3],
                            st + B_OFF + 8192 + swz(b_lb + nt2 * 2048 + ks * 32));
#pragma unroll
                for (int mt = 0; mt < 2; ++mt)
#pragma unroll
                    for (int nt = 0; nt < 4; ++nt) {
                        MmaOp<T>::run(acc[mt][nt], ah[mt],
                                      bh[nt >> 1][nt & 1], bh[nt >> 1][2 + (nt & 1)]);
                        MmaOp<T>::run(acc[mt][nt], ah[mt],
                                      bl[nt >> 1][nt & 1], bl[nt >> 1][2 + (nt & 1)]);
                        MmaOp<T>::run(acc[mt][nt], al[mt],
                                      bh[nt >> 1][nt & 1], bh[nt >> 1][2 + (nt & 1)]);
                    }
            } else {
#pragma unroll
                for (int mt = 0; mt < 2; ++mt)
#pragma unroll
                    for (int nt = 0; nt < 4; ++nt) {
                        MmaOp<T>::run(acc[mt][nt], ah[mt],
                                      bh[nt >> 1][nt & 1], bh[nt >> 1][2 + (nt & 1)]);
                        MmaOp<T>::run(acc[mt][nt], al[mt],
                                      bh[nt >> 1][nt & 1], bh[nt >> 1][2 + (nt & 1)]);
                    }
            }
        }
        __syncthreads();
        if (kt + 2 < NKT) {
            const uint32_t st2 = sb + (uint32_t)(kt & 1) * STG;
            const int ko = (kt + 2) * 64;
#pragma unroll
            for (int i = 0; i < 4; ++i) {
                cp16(st2 + asw[i], aptr[i] + ko);
                cp16(st2 + 16384 + asw[i], aptr[i] + dA + ko);
            }
#pragma unroll
            for (int i = 0; i < 2; ++i) {
                cp16(st2 + B_OFF + bsw[i], bptr[i] + ko);
                if (SPLIT_B) cp16(st2 + B_OFF + 8192 + bsw[i], bptr[i] + dB + ko);
            }
        }
        CP_COMMIT();
    }

    // epilogue
#pragma unroll
    for (int mt = 0; mt < 2; ++mt) {
        const int row = m0 + wm + mt * 16 + (lane >> 2);
#pragma unroll
        for (int nt = 0; nt < 4; ++nt) {
            const int col = n0 + wn + nt * 8 + (lane & 3) * 2;
            float* p0 = C + (size_t)row * N + col;
            *(float2*)p0 = make_float2(acc[mt][nt][0], acc[mt][nt][1]);
            *(float2*)(p0 + 8 * (size_t)N) = make_float2(acc[mt][nt][2], acc[mt][nt][3]);
        }
    }
}

// ---------------- RoPE (in place) ----------------
__global__ void rope_kernel(float* __restrict__ X, int nh) {
    const int s = blockIdx.x;
    const int d = threadIdx.x;  // 0..63
    const float e = (float)d * (1.0f / 64.0f);
    const float invf = 1.0f / powf(10000.0f, e);
    const float ang = (float)s * invf;
    float sn, cs;
    sincosf(ang, &sn, &cs);
    float* p = X + (size_t)s * nh * DH;
    for (int h = 0; h < nh; ++h) {
        const float x1 = p[d];
        const float x2 = p[d + 64];
        p[d] = x1 * cs - x2 * sn;
        p[d + 64] = x2 * cs + x1 * sn;
        p += DH;
    }
}

// ---------------- local windowed attention ----------------
#define QP 132
#define KP 132
__global__ __launch_bounds__(256, 1)
void local_attn_kernel(const float* __restrict__ Q, const float* __restrict__ K,
                       const float* __restrict__ V, float* __restrict__ O) {
    extern __shared__ float sm[];
    float* sq = sm;                    // 64 x 132
    float* sk = sq + 64 * QP;          // 128 x 132
    float* sv = sk + 128 * KP;         // 128 x 128
    float* sc = sv + 128 * 128;        // 64 x 66

    const int tid = threadIdx.x;
    const int h = blockIdx.y;
    const int n = blockIdx.x;
    const int kvh = h >> 2;
    const int q0 = n * 64;
    const int key0 = q0 - 64;

#pragma unroll
    for (int it = 0; it < 8; ++it) {
        int idx = tid + it * 256;
        int r = idx >> 5, c4 = idx & 31;
        float4 v4 = *(const float4*)&Q[(size_t)(q0 + r) * (NH * DH) + h * DH + c4 * 4];
        *(float4*)&sq[r * QP + c4 * 4] = v4;
    }
#pragma unroll
    for (int it = 0; it < 16; ++it) {
        int idx = tid + it * 256;
        int r = idx >> 5, c4 = idx & 31;
        int pos = key0 + r;
        float4 kv = make_float4(0.f, 0.f, 0.f, 0.f);
        float4 vv = make_float4(0.f, 0.f, 0.f, 0.f);
        if (pos >= 0) {
            kv = *(const float4*)&K[(size_t)pos * (NKV * DH) + kvh * DH + c4 * 4];
            vv = *(const float4*)&V[(size_t)pos * (NKV * DH) + kvh * DH + c4 * 4];
        }
        *(float4*)&sk[r * KP + c4 * 4] = kv;
        *(float4*)&sv[r * 128 + c4 * 4] = vv;
    }
    __syncthreads();

    {
        const int i = tid >> 2;
        const int jo = tid & 3;
        float s[16];
        float s64 = 0.f;
#pragma unroll
        for (int m = 0; m < 16; ++m) s[m] = 0.f;
        const float* qrow = sq + i * QP;
        for (int d0 = 0; d0 < 128; d0 += 8) {
            float qv[8];
            *(float4*)&qv[0] = *(const float4*)&qrow[d0];
            *(float4*)&qv[4] = *(const float4*)&qrow[d0 + 4];
#pragma unroll
            for (int m = 0; m < 16; ++m) {
                const float* kr = sk + (i + jo + 4 * m) * KP + d0;
#pragma unroll
                for (int dd = 0; dd < 8; ++dd) s[m] = fmaf(qv[dd], kr[dd], s[m]);
            }
            if (jo == 0) {
                const float* kr = sk + (i + 64) * KP + d0;
#pragma unroll
                for (int dd = 0; dd < 8; ++dd) s64 = fmaf(qv[dd], kr[dd], s64);
            }
        }
#pragma unroll
        for (int m = 0; m < 16; ++m) sc[i * 66 + jo + 4 * m] = s[m] * ATT_SCALE;
        if (jo == 0) sc[i * 66 + 64] = s64 * ATT_SCALE;
    }
    __syncthreads();

    if (tid < 64) {
        float* row = sc + tid * 66;
        float mx = row[0];
        for (int j = 1; j < 65; ++j) mx = fmaxf(mx, row[j]);
        float sum = 0.f;
        for (int j = 0; j < 65; ++j) {
            float ex = expf(row[j] - mx);
            row[j] = ex;
            sum += ex;
        }
        float inv = 1.f / sum;
        for (int j = 0; j < 65; ++j) row[j] *= inv;
    }
    __syncthreads();

    {
        const int w = tid >> 5, lane = tid & 31;
        const float4* sv4 = (const float4*)sv;
        for (int iq = 0; iq < 8; ++iq) {
            const int i = w * 8 + iq;
            const float* wrow = sc + i * 66;
            float4 o = make_float4(0.f, 0.f, 0.f, 0.f);
#pragma unroll 5
            for (int jj = 0; jj < 65; ++jj) {
                float wt = wrow[jj];
                float4 v4 = sv4[(i + jj) * 32 + lane];
                o.x = fmaf(wt, v4.x, o.x);
                o.y = fmaf(wt, v4.y, o.y);
                o.z = fmaf(wt, v4.z, o.z);
                o.w = fmaf(wt, v4.w, o.w);
            }
            float4 res = make_float4(0.7f * o.x, 0.7f * o.y, 0.7f * o.z, 0.7f * o.w);
            *(float4*)&O[(size_t)(q0 + i) * (NH * DH) + h * DH + lane * 4] = res;
        }
    }
}

// ---------------- landmark attention (adds 0.3*global, writes fp16 hi/lo) ----------------
__global__ __launch_bounds__(256, 1)
void lm_attn_kernel(const float* __restrict__ Q, const float* __restrict__ K,
                    const float* __restrict__ V, const float* __restrict__ OL,
                    __half* __restrict__ atHi, __half* __restrict__ atLo) {
    extern __shared__ float sm[];
    float* sq = sm;                    // 64 x 132
    float* slk = sq + 64 * QP;         // 64 x 132
    float* slv = slk + 64 * QP;        // 64 x 128
    float* sc = slv + 64 * 128;        // 64 x 66

    const int tid = threadIdx.x;
    const int h = blockIdx.y;
    const int c = blockIdx.x;
    const int kvh = h >> 2;
    const int q0 = c * 64;
    const int nvis = c + 1;

#pragma unroll
    for (int it = 0; it < 8; ++it) {
        int idx = tid + it * 256;
        int r = idx >> 5, c4 = idx & 31;
        *(float4*)&sq[r * QP + c4 * 4] =
            *(const float4*)&Q[(size_t)(q0 + r) * (NH * DH) + h * DH + c4 * 4];
    }
#pragma unroll
    for (int it = 0; it < 8; ++it) {
        int idx = tid + it * 256;
        int r = idx >> 5, c4 = idx & 31;
        int pos = r * 64;
        *(float4*)&slk[r * QP + c4 * 4] =
            *(const float4*)&K[(size_t)pos * (NKV * DH) + kvh * DH + c4 * 4];
        *(float4*)&slv[r * 128 + c4 * 4] =
            *(const float4*)&V[(size_t)pos * (NKV * DH) + kvh * DH + c4 * 4];
    }
    __syncthreads();

    {
        const int i = tid >> 2;
        const int jo = tid & 3;
        float s[16];
#pragma unroll
        for (int m = 0; m < 16; ++m) s[m] = 0.f;
        const float* qrow = sq + i * QP;
        for (int d0 = 0; d0 < 128; d0 += 8) {
            float qv[8];
            *(float4*)&qv[0] = *(const float4*)&qrow[d0];
            *(float4*)&qv[4] = *(const float4*)&qrow[d0 + 4];
#pragma unroll
            for (int m = 0; m < 16; ++m) {
                const float* kr = slk + (jo + 4 * m) * QP + d0;
#pragma unroll
                for (int dd = 0; dd < 8; ++dd) s[m] = fmaf(qv[dd], kr[dd], s[m]);
            }
        }
#pragma unroll
        for (int m = 0; m < 16; ++m) {
            int jj = jo + 4 * m;
            if (jj < nvis) sc[i * 66 + jj] = s[m] * ATT_SCALE;
        }
    }
    __syncthreads();

    if (tid < 64) {
        float* row = sc + tid * 66;
        float mx = row[0];
        for (int j = 1; j < nvis; ++j) mx = fmaxf(mx, row[j]);
        float sum = 0.f;
        for (int j = 0; j < nvis; ++j) {
            float ex = expf(row[j] - mx);
            row[j] = ex;
            sum += ex;
        }
        float inv = 1.f / sum;
        for (int j = 0; j < nvis; ++j) row[j] *= inv;
    }
    __syncthreads();

    {
        const int w = tid >> 5, lane = tid & 31;
        const float4* slv4 = (const float4*)slv;
        for (int iq = 0; iq < 8; ++iq) {
            const int i = w * 8 + iq;
            const float* wrow = sc + i * 66;
            float4 o = make_float4(0.f, 0.f, 0.f, 0.f);
            for (int jj = 0; jj < nvis; ++jj) {
                float wt = wrow[jj];
                float4 v4 = slv4[jj * 32 + lane];
                o.x = fmaf(wt, v4.x, o.x);
                o.y = fmaf(wt, v4.y, o.y);
                o.z = fmaf(wt, v4.z, o.z);
                o.w = fmaf(wt, v4.w, o.w);
            }
            size_t idx = (size_t)(q0 + i) * (NH * DH) + h * DH + lane * 4;
            float4 old = *(const float4*)&OL[idx];
            float s4[4] = {old.x + 0.3f * o.x, old.y + 0.3f * o.y,
                           old.z + 0.3f * o.z, old.w + 0.3f * o.w};
            union { __half b[4]; uint2 u; } H, L;
#pragma unroll
            for (int q = 0; q < 4; ++q) {
                __half hb = __float2half_rn(s4[q]);
                H.b[q] = hb;
                L.b[q] = __float2half_rn(s4[q] - __half2float(hb));
            }
            *(uint2*)&atHi[idx] = H.u;
            *(uint2*)&atLo[idx] = L.u;
        }
    }
}

// ---------------- launch ----------------
extern "C" void kernel_launch(void* const* d_in, const int* in_sizes, int n_in,
                              void* d_out, int out_size) {
    const float* hs = (const float*)d_in[0];
    const float* wq = (const float*)d_in[1];
    const float* wk = (const float*)d_in[2];
    const float* wv = (const float*)d_in[3];
    const float* wo = (const float*)d_in[4];
    float* out = (float*)d_out;

    float *Q, *K, *V, *AT;
    __nv_bfloat16 *hsHi, *hsLo, *wqTHi, *wqTLo, *wkTHi, *wkTLo, *wvTHi, *wvTLo;
    __half *woT16, *at16h, *at16l;
    cudaGetSymbolAddress((void**)&Q, g_Q);
    cudaGetSymbolAddress((void**)&K, g_K);
    cudaGetSymbolAddress((void**)&V, g_V);
    cudaGetSymbolAddress((void**)&AT, g_attn);
    cudaGetSymbolAddress((void**)&hsHi, g_hsHi);
    cudaGetSymbolAddress((void**)&hsLo, g_hsLo);
    cudaGetSymbolAddress((void**)&wqTHi, g_wqTHi);
    cudaGetSymbolAddress((void**)&wqTLo, g_wqTLo);
    cudaGetSymbolAddress((void**)&wkTHi, g_wkTHi);
    cudaGetSymbolAddress((void**)&wkTLo, g_wkTLo);
    cudaGetSymbolAddress((void**)&wvTHi, g_wvTHi);
    cudaGetSymbolAddress((void**)&wvTLo, g_wvTLo);
    cudaGetSymbolAddress((void**)&woT16, g_woT16);
    cudaGetSymbolAddress((void**)&at16h, g_at16h);
    cudaGetSymbolAddress((void**)&at16l, g_at16l);

    const int SMEM_LOCAL = (64 * QP + 128 * KP + 128 * 128 + 64 * 66) * 4;
    const int SMEM_LM = (64 * QP + 64 * QP + 64 * 128 + 64 * 66) * 4;
    const int SMEM_G3 = 2 * (32768 + 16384);  // 98304
    const int SMEM_G2 = 2 * (32768 + 8192);   // 81920
    cudaFuncSetAttribute(local_attn_kernel, cudaFuncAttributeMaxDynamicSharedMemorySize, SMEM_LOCAL);
    cudaFuncSetAttribute(lm_attn_kernel, cudaFuncAttributeMaxDynamicSharedMemorySize, SMEM_LM);
    cudaFuncSetAttribute(gemm_tc<__nv_bfloat16, true>,
                         cudaFuncAttributeMaxDynamicSharedMemorySize, SMEM_G3);
    cudaFuncSetAttribute(gemm_tc<__half, false>,
                         cudaFuncAttributeMaxDynamicSharedMemorySize, SMEM_G2);

    // launches 1-4: conversions needed by Q gemm
    split_kernel<<<(S_LEN * HID) / 1024, 256>>>(hs, hsHi, hsLo);
    transpose_split_kernel<<<dim3(HID / 32, HID / 32), dim3(32, 8)>>>(wq, wqTHi, wqTLo, HID, HID);
    transpose_split_kernel<<<dim3((NKV * DH) / 32, HID / 32), dim3(32, 8)>>>(wk, wkTHi, wkTLo, HID, NKV * DH);
    transpose_split_kernel<<<dim3((NKV * DH) / 32, HID / 32), dim3(32, 8)>>>(wv, wvTHi, wvTLo, HID, NKV * DH);

    // launch 5: Q gemm (ncu -s 5 captures this one)
    gemm_tc<__nv_bfloat16, true><<<dim3((NH * DH) / 64, S_LEN / 128), 256, SMEM_G3>>>(
        hsHi, hsLo, wqTHi, wqTLo, Q, NH * DH, HID);

    transpose_f16_kernel<<<dim3(HID / 32, HID / 32), dim3(32, 8)>>>(wo, woT16, HID, HID);

    gemm_tc<__nv_bfloat16, true><<<dim3((NKV * DH) / 64, S_LEN / 128), 256, SMEM_G3>>>(
        hsHi, hsLo, wkTHi, wkTLo, K, NKV * DH, HID);
    gemm_tc<__nv_bfloat16, true><<<dim3((NKV * DH) / 64, S_LEN / 128), 256, SMEM_G3>>>(
        hsHi, hsLo, wvTHi, wvTLo, V, NKV * DH, HID);

    rope_kernel<<<S_LEN, 64>>>(Q, NH);
    rope_kernel<<<S_LEN, 64>>>(K, NKV);

    local_attn_kernel<<<dim3(S_LEN / 64, NH), 256, SMEM_LOCAL>>>(Q, K, V, AT);
    lm_attn_kernel<<<dim3(S_LEN / 64, NH), 256, SMEM_LM>>>(Q, K, V, AT, at16h, at16l);

    // O projection: fp16 2-pass (A split, B single-rounded)
    gemm_tc<__half, false><<<dim3(HID / 64, S_LEN / 128), 256, SMEM_G2>>>(
        at16h, at16l, woT16, (const __half*)nullptr, out, HID, HID);
}